// round 10
// baseline (speedup 1.0000x reference)
#include <cuda_runtime.h>

// out[p, :] = cumsum(W, axis=1)[:, x[p]] + b, p in [0, 8192*200)
// x: int32 (NPOS), W: fp32 (64,129) row-major, b: fp32 (64), out: fp32 (NPOS*64)

#define F1 129                  // num_feature + 1
#define D  64                   // vector dim
#define NPOS (8192 * 200)       // 1,638,400 positions (divisible by 32)
#define TPB 512                 // 16 warps per CTA
#define WARPS_PB (TPB / 32)

__global__ void __launch_bounds__(TPB, 4)
embed_kernel(const int* __restrict__ x,
             const float* __restrict__ W,
             const float* __restrict__ b,
             float* __restrict__ out) {
    // tab[c*64 + d] = b[d] + sum_{j<=c} W[d*F1 + j]; 33,024 B
    __shared__ float tab[F1 * D];
    __shared__ float carry[8][D];

    // ---- in-CTA parallel build: 512 threads = 8 segments x 64 dims ----
    {
        const int t   = threadIdx.x;
        const int d   = t & 63;
        const int seg = t >> 6;                 // 0..7
        const int start = seg * 16;             // 16 elems/segment; elem 128 handled by seg 7
        const int cnt   = (seg == 7) ? 17 : 16; // seg 7 covers 112..128

        // Pass 1: stage raw W + per-segment sum (batched loads)
        const float* wrow = W + d * F1 + start;
        float s = 0.f;
        #pragma unroll
        for (int j = 0; j < 16; ++j) {
            float v = __ldg(&wrow[j]);
            s += v;
            tab[(start + j) * D + d] = v;
        }
        if (cnt == 17) {
            float v = __ldg(&wrow[16]);
            s += v;
            tab[(start + 16) * D + d] = v;
        }
        carry[seg][d] = s;
        __syncthreads();

        // Pass 2: carry-in + in-smem prefix chain over this segment
        float p = __ldg(&b[d]);
        #pragma unroll
        for (int q = 0; q < 7; ++q)
            if (q < seg) p += carry[q][d];
        for (int j = 0; j < cnt; ++j) {
            p += tab[(start + j) * D + d];
            tab[(start + j) * D + d] = p;
        }
        __syncthreads();
    }

    const float4* tab4 = reinterpret_cast<const float4*>(tab);

    // ---- gather/store loop (store-bound; ~5.1 TB/s write ceiling) ----
    const int lane   = threadIdx.x & 31;
    const int lane15 = lane & 15;          // which float4 within the 64-float row
    const int half   = lane >> 4;          // 0/1: which of each pair of positions
    const int warp   = threadIdx.x >> 5;

    const int gwarp  = blockIdx.x * WARPS_PB + warp;
    const int nwarps = gridDim.x * WARPS_PB;
    const int stride = nwarps * 32;
    float4* __restrict__ o4 = reinterpret_cast<float4*>(out);

    #pragma unroll 1
    for (int base = gwarp * 32; base < NPOS; base += stride) {
        // x read once: evict-first, keep it out of the caches
        const int xv = __ldcs(&x[base + lane]);        // coalesced 128B

        // warp covers 32 consecutive positions; store addrs = wbase + k*512B
        float4* wbase = o4 + ((size_t)base + half) * (D / 4) + lane15;
        #pragma unroll
        for (int k = 0; k < 16; ++k) {
            const int xi = __shfl_sync(0xffffffffu, xv, 2 * k + half);
            const float4 v = tab4[xi * (D / 4) + lane15];
            __stcs(wbase + k * 2 * (D / 4), v);        // streaming store
        }
    }
}

extern "C" void kernel_launch(void* const* d_in, const int* in_sizes, int n_in,
                              void* d_out, int out_size) {
    const int*   x = (const int*)  d_in[0];
    const float* W = (const float*)d_in[1];
    const float* b = (const float*)d_in[2];
    float*     out = (float*)d_out;

    // Single node: 152 SMs * 4 CTAs of 512 threads (64 warps/SM, 134KB smem/SM)
    const int grid = 152 * 4;
    embed_kernel<<<grid, TPB>>>(x, W, b, out);
}